// round 9
// baseline (speedup 1.0000x reference)
#include <cuda_runtime.h>
#include <cuda_fp16.h>
#include <cstdint>
#include <cstddef>

#define NHEAD 8
#define HID 512
#define DK 64
#define SEQ 1024
#define BATCH 4
#define TOK 4096
#define WIN 34
#define KDIM 512

#define BK 64
#define OFF_B 16384
#define STAGE_B 32768                  // A | B
#define GSMEM (3 * STAGE_B)            // 98304, 3-stage pipeline
#define NCTA 296

// ---------------- scratch ----------------
__device__ float g_st  [2ull * TOK * HID];
__device__ float g_qkv [2ull * TOK * 3 * HID];
__device__ float g_y   [2ull * TOK * HID];
__device__ __half g_act_h [2ull * TOK * HID];
__device__ __half g_attn_h[2ull * TOK * HID];
__device__ __half g_yh    [2ull * TOK * HID];
__device__ __half g_y2h   [2ull * TOK * HID];
__device__ __half g_wqkv  [4194304];
__device__ __half g_whw   [4194304];

// ---------------- helpers ----------------
__device__ __forceinline__ uint32_t s2u(const void* p) {
    uint32_t a;
    asm("{ .reg .u64 t; cvta.to.shared.u64 t, %1; cvt.u32.u64 %0, t; }" : "=r"(a) : "l"(p));
    return a;
}
__device__ __forceinline__ void cpasync16(uint32_t dst, const void* src) {
    asm volatile("cp.async.cg.shared.global [%0], [%1], 16;" :: "r"(dst), "l"(src));
}
__device__ __forceinline__ void ldmx4(uint32_t* d, uint32_t a) {
    asm volatile("ldmatrix.sync.aligned.m8n8.x4.shared.b16 {%0,%1,%2,%3}, [%4];"
        : "=r"(d[0]), "=r"(d[1]), "=r"(d[2]), "=r"(d[3]) : "r"(a));
}
__device__ __forceinline__ void mma16816(float* c, const uint32_t* a, const uint32_t* b) {
    asm volatile("mma.sync.aligned.m16n8k16.row.col.f32.f16.f16.f32 "
        "{%0,%1,%2,%3}, {%4,%5,%6,%7}, {%8,%9}, {%0,%1,%2,%3};"
        : "+f"(c[0]), "+f"(c[1]), "+f"(c[2]), "+f"(c[3])
        : "r"(a[0]), "r"(a[1]), "r"(a[2]), "r"(a[3]), "r"(b[0]), "r"(b[1]));
}
__device__ __forceinline__ uint32_t pack_h2(float x, float y) {
    __half2 t = __floats2half2_rn(x, y);
    return *(uint32_t*)&t;
}

// ---------------- weight conversion: fp32 -> fp16 ----------------
__global__ void conv_w(const float* __restrict__ src, __half* __restrict__ dst)
{
    const size_t i = (size_t)blockIdx.x * blockDim.x + threadIdx.x;
    float4 v = ((const float4*)src)[i];
    *(uint2*)(dst + 4 * i) = make_uint2(pack_h2(v.x, v.y), pack_h2(v.z, v.w));
}

// highway weights: interleave rows so out col 2j=nonlin_j, 2j+1=gate_j
__global__ void conv_hw(const float* __restrict__ src, __half* __restrict__ dst)
{
    const size_t idx = (size_t)blockIdx.x * blockDim.x + threadIdx.x;
    const size_t m   = idx >> 17;
    const size_t rem = idx & 131071;
    const int    r   = (int)(rem >> 7);
    const size_t c4  = rem & 127;
    const int dr = (r < 512) ? (2 * r) : (2 * (r - 512) + 1);
    float4 v = ((const float4*)src)[idx];
    const size_t d = (m << 17) + (size_t)dr * 128 + c4;
    *(uint2*)(dst + 4 * d) = make_uint2(pack_h2(v.x, v.y), pack_h2(v.z, v.w));
}

// ---------------- persistent fused HMMA GEMM ----------------
// CTA 128x128, 128 threads, 2x2 warps, warp tile 64x64 (MMA:LDSM ratio 4.0).
// BK=64, 3-stage cp.async, one barrier per chunk, prefetch g+2.
__global__ __launch_bounds__(128)
void gemm_fused(const __half* __restrict__ A, const __half* __restrict__ B,
                const float* __restrict__ bias, float* __restrict__ C,
                __half* __restrict__ Sh,
                float* __restrict__ Yv, float* __restrict__ St, float* __restrict__ Out,
                int N, size_t sB, size_t sbias, size_t sC, int mode, int add_res,
                int ntiles)
{
    extern __shared__ char smem[];
    const uint32_t sbase = s2u(smem);
    const int tid = threadIdx.x, lane = tid & 31, wid = tid >> 5;
    const int wm = wid & 1, wn = wid >> 1;

    const int bx = (int)blockIdx.x;
    const int nt = (bx < ntiles) ? ((ntiles - 1 - bx) / (int)gridDim.x + 1) : 0;
    if (nt == 0) return;
    const int total = nt * 8;

    // cp.async coords: thread t covers row t (128 rows), 8 16B-units per array
    const uint32_t t7 = (uint32_t)(tid & 7);
    uint32_t swzu[8];
#pragma unroll
    for (int u = 0; u < 8; u++)
        swzu[u] = (uint32_t)tid * 128 + ((((uint32_t)u) ^ t7) << 4);

    // ldmatrix coords (SW128: col16 ^= row&7)
    const int m8 = lane >> 3, l7 = lane & 7;
    const uint32_t a_row = (uint32_t)(wm * 64 + (m8 & 1) * 8 + l7) * 128;
    const uint32_t b_row = (uint32_t)(wn * 64 + (m8 >> 1) * 8 + l7) * 128;
    uint32_t acol[4], bcol[4];
#pragma unroll
    for (int kk = 0; kk < 4; kk++) {
        acol[kk] = ((uint32_t)(kk * 2 + (m8 >> 1)) ^ (uint32_t)l7) << 4;
        bcol[kk] = ((uint32_t)(kk * 2 + (m8 & 1)) ^ (uint32_t)l7) << 4;
    }

    float acc[4][8][4];
#pragma unroll
    for (int i = 0; i < 4; i++)
#pragma unroll
        for (int j = 0; j < 8; j++)
#pragma unroll
            for (int k = 0; k < 4; k++) acc[i][j][k] = 0.f;

#define LOAD_G(g) do {                                                             \
        const int _t = bx + ((g) >> 3) * (int)gridDim.x;                           \
        const int _dir = _t & 1, _u = _t >> 1;                                     \
        const int _bm = (_u & 31) * 128, _bn = (_u >> 5) * 128;                    \
        const int _ke = ((g) & 7) * BK;                                            \
        const __half* _Ap = A + (size_t)_dir * (TOK * KDIM)                        \
                              + (size_t)(_bm + tid) * KDIM + _ke;                  \
        const __half* _Bp = B + (size_t)_dir * sB + (size_t)(_bn + tid) * KDIM + _ke;\
        const uint32_t _sb = sbase + (uint32_t)((g) % 3) * STAGE_B;                \
        _Pragma("unroll")                                                          \
        for (int _u8 = 0; _u8 < 8; _u8++) {                                        \
            cpasync16(_sb + swzu[_u8],         _Ap + _u8 * 8);                     \
            cpasync16(_sb + OFF_B + swzu[_u8], _Bp + _u8 * 8);                     \
        }                                                                          \
        asm volatile("cp.async.commit_group;" ::: "memory");                       \
    } while (0)

    LOAD_G(0);
    LOAD_G(1);

    const int gr = lane >> 2, gc = (lane & 3) * 2;

#pragma unroll 1
    for (int g = 0; g < total; g++) {
        if (g < total - 1) asm volatile("cp.async.wait_group 1;" ::: "memory");
        else               asm volatile("cp.async.wait_group 0;" ::: "memory");
        __syncthreads();
        if (g + 2 < total) LOAD_G(g + 2);

        const uint32_t sb = sbase + (uint32_t)(g % 3) * STAGE_B;
#pragma unroll
        for (int kk = 0; kk < 4; kk++) {
            uint32_t a[4][4], b[4][4];
#pragma unroll
            for (int nj = 0; nj < 4; nj++)
                ldmx4(b[nj], sb + OFF_B + b_row + nj * 2048 + bcol[kk]);
#pragma unroll
            for (int mi = 0; mi < 4; mi++)
                ldmx4(a[mi], sb + a_row + mi * 2048 + acol[kk]);
#pragma unroll
            for (int mi = 0; mi < 4; mi++)
#pragma unroll
                for (int ni = 0; ni < 8; ni++)
                    mma16816(acc[mi][ni], a[mi], &b[ni >> 1][(ni & 1) * 2]);
        }

        if ((g & 7) == 7) {
            // ---------------- epilogue for finished tile ----------------
            const int t = bx + (g >> 3) * (int)gridDim.x;
            const int dir = t & 1, u = t >> 1;
            const int bm = (u & 31) * 128, bn = (u >> 5) * 128;
            const float* bs = bias + (size_t)dir * sbias;

            if (mode <= 1) {
                float* Cp = C + (size_t)dir * sC;
                __half* SH = Sh ? (Sh + (size_t)dir * sC) : nullptr;
#pragma unroll
                for (int mi = 0; mi < 4; mi++) {
#pragma unroll
                    for (int ni = 0; ni < 8; ni++) {
                        const int row0 = bm + wm * 64 + mi * 16 + gr;
                        const int col  = bn + wn * 64 + ni * 8 + gc;
                        const float b0 = bs[col], b1 = bs[col + 1];
                        const float v00 = acc[mi][ni][0] + b0, v01 = acc[mi][ni][1] + b1;
                        const float v10 = acc[mi][ni][2] + b0, v11 = acc[mi][ni][3] + b1;
                        *(float2*)&Cp[(size_t)row0 * N + col]       = make_float2(v00, v01);
                        *(float2*)&Cp[(size_t)(row0 + 8) * N + col] = make_float2(v10, v11);
                        if (mode == 1) {
                            *(uint32_t*)&SH[(size_t)row0 * N + col]       = pack_h2(v00, v01);
                            *(uint32_t*)&SH[(size_t)(row0 + 8) * N + col] = pack_h2(v10, v11);
                        }
                    }
                }
            } else {
                float* Y = Yv + (size_t)dir * TOK * HID;
                float* S = St ? (St + (size_t)dir * TOK * HID) : nullptr;
                __half* SH = Sh + (size_t)dir * TOK * HID;
#pragma unroll
                for (int mi = 0; mi < 4; mi++) {
#pragma unroll
                    for (int ni = 0; ni < 8; ni++) {
                        const int row0 = bm + wm * 64 + mi * 16 + gr;
                        const int col  = bn + wn * 64 + ni * 8 + gc;
                        const int j    = col >> 1;
                        const float bnl = bs[j], bgt = bs[j + HID];
#pragma unroll
                        for (int rr = 0; rr < 2; rr++) {
                            const int row = row0 + rr * 8;
                            const float n = acc[mi][ni][rr * 2]     + bnl;
                            const float gg = acc[mi][ni][rr * 2 + 1] + bgt;
                            const size_t o = (size_t)row * HID + j;
                            const float yo = Y[o];
                            const float s = 1.f / (1.f + __expf(-gg));
                            float v = s * yo + (1.f - s) * fmaxf(n, 0.f);
                            if (mode == 2) {
                                Y[o] = v;
                            } else {
                                if (add_res) v += S[o];
                                S[o] = v;
                                Out[(size_t)row * (2 * HID) + (size_t)dir * HID + j] = v;
                            }
                            SH[o] = __float2half(v);
                        }
                    }
                }
            }
#pragma unroll
            for (int i = 0; i < 4; i++)
#pragma unroll
                for (int j = 0; j < 8; j++)
#pragma unroll
                    for (int k = 0; k < 4; k++) acc[i][j][k] = 0.f;
        }
    }
#undef LOAD_G
}

// ---------------- banded local attention v3 (conflict-free lanes) ----------
// block: 256 thr / 8 warps; 64 queries of one (b,h,dir); warp = 8 queries.
// lane l handles jj0=l (0..31) and jj1=32+l (lanes 0,1) -> consecutive LDS.
#define ATT_SMEM (17664 * 4)
__global__ void attn_v3(const float* __restrict__ rel_l)
{
    extern __shared__ float sm[];
    float* Ks = sm;               // [64][100] transposed K: d-major
    float* Vs = sm + 6400;        // [97][68]
    float* qs = sm + 12996;       // [64][68]
    float* pb = sm + 17348;       // [8][34]
    float* sbias = sm + 17620;    // [34]

    const int dir = blockIdx.z;
    const int bh = blockIdx.y;
    const int b = bh >> 3, h = bh & 7;
    const int q0 = blockIdx.x * 64;
    const int tid = threadIdx.x, w = tid >> 5, lane = tid & 31;
    const int W0 = (dir == 0) ? (q0 - 33) : q0;

    const float* base = g_qkv + (size_t)dir * TOK * (3 * HID)
                              + (size_t)(b * SEQ) * (3 * HID) + h * DK;

    if (tid < WIN)
        sbias[tid] = rel_l[((size_t)dir * NHEAD + h) * WIN + tid];

    // load q tile
    for (int idx = tid; idx < 64 * 16; idx += 256) {
        const int row = idx >> 4, dq = (idx & 15) * 4;
        const float4 v = *(const float4*)(base + (size_t)(q0 + row) * 1536 + dq);
        float* qp = qs + row * 68 + dq;
        qp[0] = v.x; qp[1] = v.y; qp[2] = v.z; qp[3] = v.w;
    }
    // load K (transposed) and V window
    for (int idx = tid; idx < 97 * 16; idx += 256) {
        const int jl = idx >> 4, dq = (idx & 15) * 4;
        const int j = W0 + jl;
        float4 kv = make_float4(0.f, 0.f, 0.f, 0.f);
        float4 vv = make_float4(0.f, 0.f, 0.f, 0.f);
        if (j >= 0 && j < SEQ) {
            kv = *(const float4*)(base + HID + (size_t)j * 1536 + dq);
            vv = *(const float4*)(base + 2 * HID + (size_t)j * 1536 + dq);
        }
        Ks[(dq + 0) * 100 + jl] = kv.x;
        Ks[(dq + 1) * 100 + jl] = kv.y;
        Ks[(dq + 2) * 100 + jl] = kv.z;
        Ks[(dq + 3) * 100 + jl] = kv.w;
        float* vp = Vs + jl * 68 + dq;
        vp[0] = vv.x; vp[1] = vv.y; vp[2] = vv.z; vp[3] = vv.w;
    }
    __syncthreads();

#pragma unroll 1
    for (int qq = 0; qq < 8; qq++) {
        const int il = w * 8 + qq;
        const int i = q0 + il;
        const int jj0 = lane;            // 0..31, always an in-band index
        const int jj1 = 32 + lane;       // valid only for lanes 0,1
        bool v0, v1;
        if (dir == 0) {
            v0 = (i - 33 + jj0 >= 0);
            v1 = (lane < 2) && (i - 33 + jj1 >= 0);
        } else {
            v0 = (i + jj0 < SEQ);
            v1 = (lane < 2) && (i + jj1 < SEQ);
        }
        const int jl0 = il + jj0;                 // <= 94
        const int jl1 = min(il + jj1, 96);
        float s0 = 0.f, s1 = 0.f;
        const float* qr = qs + il * 68;
#pragma unroll 8
        for (int d = 0; d < 64; d++) {
            const float qd = qr[d];
            s0 += qd * Ks[d * 100 + jl0];
            s1 += qd * Ks[d * 100 + jl1];
        }
        s0 = v0 ? (s0 * 0.125f + sbias[jj0]) : -1e30f;
        s1 = v1 ? (s1 * 0.125f + sbias[min(jj1, 33)]) : -1e30f;
        float m = fmaxf(s0, s1);
#pragma unroll
        for (int o = 16; o > 0; o >>= 1) m = fmaxf(m, __shfl_xor_sync(0xffffffffu, m, o));
        const float e0 = __expf(s0 - m), e1 = __expf(s1 - m);
        float den = e0 + e1;
#pragma unroll
        for (int o = 16; o > 0; o >>= 1) den += __shfl_xor_sync(0xffffffffu, den, o);
        pb[w * 34 + jj0] = e0;
        if (lane < 2) pb[w * 34 + jj1] = e1;
        __syncwarp();
        float o0 = 0.f, o1 = 0.f;
#pragma unroll 2
        for (int jj = 0; jj < WIN; jj++) {
            const float p = pb[w * 34 + jj];
            const float2 vv = *(const float2*)&Vs[(il + jj) * 68 + 2 * lane];
            o0 += p * vv.x;
            o1 += p * vv.y;
        }
        const float inv = 1.f / den;
        const size_t oi = (size_t)dir * TOK * HID + (size_t)(b * SEQ + i) * HID + h * DK + 2 * lane;
        *(uint32_t*)&g_attn_h[oi] = pack_h2(o0 * inv, o1 * inv);
        __syncwarp();
    }
}

// ---------------- init: fp16 activation (both dirs) ----------------
__global__ void init_state(const float* __restrict__ in)
{
    const size_t idx = (size_t)blockIdx.x * blockDim.x + threadIdx.x;
    const float4 v = *(const float4*)(in + idx * 4);
    const uint2 p = make_uint2(pack_h2(v.x, v.y), pack_h2(v.z, v.w));
    *(uint2*)&g_act_h[idx * 4] = p;
    *(uint2*)&g_act_h[(size_t)TOK * HID + idx * 4] = p;
}

// ---------------- launch ----------------
extern "C" void kernel_launch(void* const* d_in, const int* in_sizes, int n_in,
                              void* d_out, int out_size)
{
    const float* inputs = (const float*)d_in[0];
    const float* qkv_w  = (const float*)d_in[2];
    const float* qkv_b  = (const float*)d_in[3];
    const float* rel    = (const float*)d_in[4];
    const float* hw_w   = (const float*)d_in[5];
    const float* hw_b   = (const float*)d_in[6];
    float* out = (float*)d_out;

    float *qkvp, *yv, *st;
    __half *ah, *ath, *yh, *y2h, *wq, *wh;
    cudaGetSymbolAddress((void**)&qkvp, g_qkv);
    cudaGetSymbolAddress((void**)&yv,   g_y);
    cudaGetSymbolAddress((void**)&st,   g_st);
    cudaGetSymbolAddress((void**)&ah,   g_act_h);
    cudaGetSymbolAddress((void**)&ath,  g_attn_h);
    cudaGetSymbolAddress((void**)&yh,   g_yh);
    cudaGetSymbolAddress((void**)&y2h,  g_y2h);
    cudaGetSymbolAddress((void**)&wq,   g_wqkv);
    cudaGetSymbolAddress((void**)&wh,   g_whw);

    cudaFuncSetAttribute(gemm_fused, cudaFuncAttributeMaxDynamicSharedMemorySize, GSMEM);
    cudaFuncSetAttribute(attn_v3, cudaFuncAttributeMaxDynamicSharedMemorySize, ATT_SMEM);

    conv_w<<<4096, 256>>>(qkv_w, wq);
    conv_hw<<<4096, 256>>>(hw_w, wh);
    init_state<<<2048, 256>>>(inputs);

    for (int l = 0; l < 2; l++) {
        const size_t QL = (size_t)l * 2 * 4 * HID * HID;
        const size_t HL = (size_t)l * 2 * 2 * 2 * HID * HID;
        const float* qb = qkv_b + (size_t)l * 2 * 4 * HID;
        const float* hb = hw_b + (size_t)l * 2 * 2 * 2 * HID;

        // QKV: 768 tiles (mode 0)
        gemm_fused<<<NCTA, 128, GSMEM>>>(
            ah, wq + QL, qb, qkvp, nullptr,
            nullptr, nullptr, nullptr,
            3 * HID, (size_t)4 * HID * HID, (size_t)4 * HID, (size_t)TOK * 3 * HID, 0, 0, 768);

        attn_v3<<<dim3(SEQ / 64, BATCH * NHEAD, 2), 256, ATT_SMEM>>>(
            rel + (size_t)l * 2 * NHEAD * WIN);

        // out projection: 256 tiles (mode 1)
        gemm_fused<<<NCTA, 128, GSMEM>>>(
            ath, wq + QL + (size_t)3 * HID * HID,
            qb + 3 * HID, yv, yh, nullptr, nullptr, nullptr,
            HID, (size_t)4 * HID * HID, (size_t)4 * HID, (size_t)TOK * HID, 1, 0, 256);

        // highway 1: 512 tiles (mode 2)
        gemm_fused<<<NCTA, 128, GSMEM>>>(
            yh, wh + HL, hb, nullptr, y2h,
            yv, nullptr, nullptr,
            2 * HID, (size_t)2 * 2 * HID * HID, (size_t)2 * 2 * HID, 0, 2, 0, 512);

        // highway 2: residual + state + concat + next-layer act (mode 3)
        gemm_fused<<<NCTA, 128, GSMEM>>>(
            y2h, wh + HL + (size_t)2 * HID * HID,
            hb + 2 * HID, nullptr, ah,
            yv, st, out + (size_t)l * TOK * 2 * HID,
            2 * HID, (size_t)2 * 2 * HID * HID, (size_t)2 * 2 * HID, 0, 3, l > 0 ? 1 : 0, 512);
    }
}

// round 10
// speedup vs baseline: 1.3113x; 1.3113x over previous
#include <cuda_runtime.h>
#include <cuda_fp16.h>
#include <cstdint>
#include <cstddef>

#define NHEAD 8
#define HID 512
#define DK 64
#define SEQ 1024
#define BATCH 4
#define TOK 4096
#define WIN 34
#define KDIM 512

#define BK 64
#define OFF_B 16384
#define STAGE_B 32768                  // A | B
#define GSMEM (3 * STAGE_B)            // 98304, 3-stage pipeline
#define NCTA 296

// ---------------- scratch ----------------
__device__ float g_st  [2ull * TOK * HID];
__device__ float g_qkv [2ull * TOK * 3 * HID];
__device__ float g_y   [2ull * TOK * HID];
__device__ __half g_act_h [2ull * TOK * HID];
__device__ __half g_attn_h[2ull * TOK * HID];
__device__ __half g_yh    [2ull * TOK * HID];
__device__ __half g_y2h   [2ull * TOK * HID];
__device__ __half g_wqkv  [4194304];
__device__ __half g_whw   [4194304];

// ---------------- helpers ----------------
__device__ __forceinline__ uint32_t s2u(const void* p) {
    uint32_t a;
    asm("{ .reg .u64 t; cvta.to.shared.u64 t, %1; cvt.u32.u64 %0, t; }" : "=r"(a) : "l"(p));
    return a;
}
__device__ __forceinline__ void cpasync16(uint32_t dst, const void* src) {
    asm volatile("cp.async.cg.shared.global [%0], [%1], 16;" :: "r"(dst), "l"(src));
}
__device__ __forceinline__ void ldmx4(uint32_t* d, uint32_t a) {
    asm volatile("ldmatrix.sync.aligned.m8n8.x4.shared.b16 {%0,%1,%2,%3}, [%4];"
        : "=r"(d[0]), "=r"(d[1]), "=r"(d[2]), "=r"(d[3]) : "r"(a));
}
__device__ __forceinline__ void mma16816(float* c, const uint32_t* a, const uint32_t* b) {
    asm volatile("mma.sync.aligned.m16n8k16.row.col.f32.f16.f16.f32 "
        "{%0,%1,%2,%3}, {%4,%5,%6,%7}, {%8,%9}, {%0,%1,%2,%3};"
        : "+f"(c[0]), "+f"(c[1]), "+f"(c[2]), "+f"(c[3])
        : "r"(a[0]), "r"(a[1]), "r"(a[2]), "r"(a[3]), "r"(b[0]), "r"(b[1]));
}
__device__ __forceinline__ uint32_t pack_h2(float x, float y) {
    __half2 t = __floats2half2_rn(x, y);
    return *(uint32_t*)&t;
}

// ---------------- weight conversion (merged): fp32 -> fp16 ----------------
// grid 8192: bx<4096 -> qkv weights (plain), else highway weights (row-interleaved)
__global__ void conv_all(const float* __restrict__ qkvw, const float* __restrict__ hww,
                         __half* __restrict__ dq, __half* __restrict__ dh)
{
    const size_t bi = blockIdx.x;
    if (bi < 4096) {
        const size_t i = bi * blockDim.x + threadIdx.x;
        float4 v = ((const float4*)qkvw)[i];
        *(uint2*)(dq + 4 * i) = make_uint2(pack_h2(v.x, v.y), pack_h2(v.z, v.w));
    } else {
        const size_t idx = (bi - 4096) * blockDim.x + threadIdx.x;
        const size_t m   = idx >> 17;
        const size_t rem = idx & 131071;
        const int    r   = (int)(rem >> 7);
        const size_t c4  = rem & 127;
        const int dr = (r < 512) ? (2 * r) : (2 * (r - 512) + 1);
        float4 v = ((const float4*)hww)[idx];
        const size_t d = (m << 17) + (size_t)dr * 128 + c4;
        *(uint2*)(dh + 4 * d) = make_uint2(pack_h2(v.x, v.y), pack_h2(v.z, v.w));
    }
}

// ---------------- persistent fused HMMA GEMM (R8 config restored) ----------
// CTA 128x128, 256 threads, 2x4 warps, warp tile 64x32, BK=64, 3-stage cp.async.
__global__ __launch_bounds__(256, 2)
void gemm_fused(const __half* __restrict__ A, const __half* __restrict__ B,
                const float* __restrict__ bias, float* __restrict__ C,
                __half* __restrict__ Sh,
                float* __restrict__ Yv, float* __restrict__ St, float* __restrict__ Out,
                int N, size_t sB, size_t sbias, size_t sC, int mode, int add_res,
                int ntiles)
{
    extern __shared__ char smem[];
    const uint32_t sbase = s2u(smem);
    const int tid = threadIdx.x, lane = tid & 31, wid = tid >> 5;
    const int wm = wid & 1, wn = wid >> 1;

    const int bx = (int)blockIdx.x;
    const int nt = (bx < ntiles) ? ((ntiles - 1 - bx) / (int)gridDim.x + 1) : 0;
    if (nt == 0) return;
    const int total = nt * 8;

    // cp.async coords: 128 rows x 8 16B-units; 4 units per thread per array
    const int r  = tid >> 1;
    const int c0 = (tid & 1) * 4;
    const uint32_t r7 = (uint32_t)(r & 7);
    uint32_t swz[4];
#pragma unroll
    for (int u = 0; u < 4; u++)
        swz[u] = (uint32_t)r * 128 + ((((uint32_t)(c0 + u)) ^ r7) << 4);

    // ldmatrix coords (SW128: col16 ^= row&7)
    const int m8 = lane >> 3, l7 = lane & 7;
    const uint32_t a_row = (uint32_t)(wm * 64 + (m8 & 1) * 8 + l7) * 128;
    const uint32_t b_row = (uint32_t)(wn * 32 + (m8 >> 1) * 8 + l7) * 128;
    uint32_t acol[4], bcol[4];
#pragma unroll
    for (int kk = 0; kk < 4; kk++) {
        acol[kk] = ((uint32_t)(kk * 2 + (m8 >> 1)) ^ (uint32_t)l7) << 4;
        bcol[kk] = ((uint32_t)(kk * 2 + (m8 & 1)) ^ (uint32_t)l7) << 4;
    }

    float acc[4][4][4];
#pragma unroll
    for (int i = 0; i < 4; i++)
#pragma unroll
        for (int j = 0; j < 4; j++)
#pragma unroll
            for (int k = 0; k < 4; k++) acc[i][j][k] = 0.f;

#define LOAD_G(g) do {                                                             \
        const int _t = bx + ((g) >> 3) * (int)gridDim.x;                           \
        const int _dir = _t & 1, _u = _t >> 1;                                     \
        const int _bm = (_u & 31) * 128, _bn = (_u >> 5) * 128;                    \
        const int _ke = ((g) & 7) * BK + c0 * 8;                                   \
        const __half* _Ap = A + (size_t)_dir * (TOK * KDIM)                        \
                              + (size_t)(_bm + r) * KDIM + _ke;                    \
        const __half* _Bp = B + (size_t)_dir * sB + (size_t)(_bn + r) * KDIM + _ke;\
        const uint32_t _sb = sbase + (uint32_t)((g) % 3) * STAGE_B;                \
        cpasync16(_sb + swz[0],         _Ap);                                      \
        cpasync16(_sb + swz[1],         _Ap + 8);                                  \
        cpasync16(_sb + swz[2],         _Ap + 16);                                 \
        cpasync16(_sb + swz[3],         _Ap + 24);                                 \
        cpasync16(_sb + OFF_B + swz[0], _Bp);                                      \
        cpasync16(_sb + OFF_B + swz[1], _Bp + 8);                                  \
        cpasync16(_sb + OFF_B + swz[2], _Bp + 16);                                 \
        cpasync16(_sb + OFF_B + swz[3], _Bp + 24);                                 \
        asm volatile("cp.async.commit_group;" ::: "memory");                       \
    } while (0)

    LOAD_G(0);
    LOAD_G(1);

    const int gr = lane >> 2, gc = (lane & 3) * 2;

#pragma unroll 1
    for (int g = 0; g < total; g++) {
        if (g < total - 1) asm volatile("cp.async.wait_group 1;" ::: "memory");
        else               asm volatile("cp.async.wait_group 0;" ::: "memory");
        __syncthreads();
        if (g + 2 < total) LOAD_G(g + 2);

        const uint32_t sb = sbase + (uint32_t)(g % 3) * STAGE_B;
#pragma unroll
        for (int kk = 0; kk < 4; kk++) {
            uint32_t a[4][4], b[2][4];
#pragma unroll
            for (int nj = 0; nj < 2; nj++)
                ldmx4(b[nj], sb + OFF_B + b_row + nj * 2048 + bcol[kk]);
#pragma unroll
            for (int mi = 0; mi < 4; mi++)
                ldmx4(a[mi], sb + a_row + mi * 2048 + acol[kk]);
#pragma unroll
            for (int mi = 0; mi < 4; mi++)
#pragma unroll
                for (int ni = 0; ni < 4; ni++)
                    mma16816(acc[mi][ni], a[mi], &b[ni >> 1][(ni & 1) * 2]);
        }

        if ((g & 7) == 7) {
            const int t = bx + (g >> 3) * (int)gridDim.x;
            const int dir = t & 1, u = t >> 1;
            const int bm = (u & 31) * 128, bn = (u >> 5) * 128;
            const float* bs = bias + (size_t)dir * sbias;

            if (mode <= 1) {
                float* Cp = C + (size_t)dir * sC;
                __half* SH = Sh ? (Sh + (size_t)dir * sC) : nullptr;
#pragma unroll
                for (int mi = 0; mi < 4; mi++) {
#pragma unroll
                    for (int ni = 0; ni < 4; ni++) {
                        const int row0 = bm + wm * 64 + mi * 16 + gr;
                        const int col  = bn + wn * 32 + ni * 8 + gc;
                        const float b0 = bs[col], b1 = bs[col + 1];
                        const float v00 = acc[mi][ni][0] + b0, v01 = acc[mi][ni][1] + b1;
                        const float v10 = acc[mi][ni][2] + b0, v11 = acc[mi][ni][3] + b1;
                        *(float2*)&Cp[(size_t)row0 * N + col]       = make_float2(v00, v01);
                        *(float2*)&Cp[(size_t)(row0 + 8) * N + col] = make_float2(v10, v11);
                        if (mode == 1) {
                            *(uint32_t*)&SH[(size_t)row0 * N + col]       = pack_h2(v00, v01);
                            *(uint32_t*)&SH[(size_t)(row0 + 8) * N + col] = pack_h2(v10, v11);
                        }
                    }
                }
            } else {
                float* Y = Yv + (size_t)dir * TOK * HID;
                float* S = St ? (St + (size_t)dir * TOK * HID) : nullptr;
                __half* SH = Sh + (size_t)dir * TOK * HID;
#pragma unroll
                for (int mi = 0; mi < 4; mi++) {
#pragma unroll
                    for (int ni = 0; ni < 4; ni++) {
                        const int row0 = bm + wm * 64 + mi * 16 + gr;
                        const int col  = bn + wn * 32 + ni * 8 + gc;
                        const int j    = col >> 1;
                        const float bnl = bs[j], bgt = bs[j + HID];
#pragma unroll
                        for (int rr = 0; rr < 2; rr++) {
                            const int row = row0 + rr * 8;
                            const float n = acc[mi][ni][rr * 2]     + bnl;
                            const float gg = acc[mi][ni][rr * 2 + 1] + bgt;
                            const size_t o = (size_t)row * HID + j;
                            const float yo = Y[o];
                            const float s = 1.f / (1.f + __expf(-gg));
                            float v = s * yo + (1.f - s) * fmaxf(n, 0.f);
                            if (mode == 2) {
                                Y[o] = v;
                            } else {
                                if (add_res) v += S[o];
                                S[o] = v;
                                Out[(size_t)row * (2 * HID) + (size_t)dir * HID + j] = v;
                            }
                            SH[o] = __float2half(v);
                        }
                    }
                }
            }
#pragma unroll
            for (int i = 0; i < 4; i++)
#pragma unroll
                for (int j = 0; j < 4; j++)
#pragma unroll
                    for (int k = 0; k < 4; k++) acc[i][j][k] = 0.f;
        }
    }
#undef LOAD_G
}

// ---------------- banded local attention v4 (shuffle broadcast, no pb smem) --
// block: 256 thr / 8 warps; 64 queries of one (b,h,dir); warp = 8 queries.
// lane l: scores jj0=l (0..31) and jj1=32+l (lanes 0,1); probs broadcast via shfl.
#define ATT_SMEM (17384 * 4)
__global__ void attn_v4(const float* __restrict__ rel_l)
{
    extern __shared__ float sm[];
    float* Ks = sm;               // [64][100] transposed K: d-major
    float* Vs = sm + 6400;        // [97][68]
    float* qs = sm + 12996;       // [64][68]
    float* sbias = sm + 17348;    // [34]

    const int dir = blockIdx.z;
    const int bh = blockIdx.y;
    const int b = bh >> 3, h = bh & 7;
    const int q0 = blockIdx.x * 64;
    const int tid = threadIdx.x, w = tid >> 5, lane = tid & 31;
    const int W0 = (dir == 0) ? (q0 - 33) : q0;

    const float* base = g_qkv + (size_t)dir * TOK * (3 * HID)
                              + (size_t)(b * SEQ) * (3 * HID) + h * DK;

    if (tid < WIN)
        sbias[tid] = rel_l[((size_t)dir * NHEAD + h) * WIN + tid];

    // load q tile
    for (int idx = tid; idx < 64 * 16; idx += 256) {
        const int row = idx >> 4, dq = (idx & 15) * 4;
        const float4 v = *(const float4*)(base + (size_t)(q0 + row) * 1536 + dq);
        float* qp = qs + row * 68 + dq;
        qp[0] = v.x; qp[1] = v.y; qp[2] = v.z; qp[3] = v.w;
    }
    // load K (transposed) and V window
    for (int idx = tid; idx < 97 * 16; idx += 256) {
        const int jl = idx >> 4, dq = (idx & 15) * 4;
        const int j = W0 + jl;
        float4 kv = make_float4(0.f, 0.f, 0.f, 0.f);
        float4 vv = make_float4(0.f, 0.f, 0.f, 0.f);
        if (j >= 0 && j < SEQ) {
            kv = *(const float4*)(base + HID + (size_t)j * 1536 + dq);
            vv = *(const float4*)(base + 2 * HID + (size_t)j * 1536 + dq);
        }
        Ks[(dq + 0) * 100 + jl] = kv.x;
        Ks[(dq + 1) * 100 + jl] = kv.y;
        Ks[(dq + 2) * 100 + jl] = kv.z;
        Ks[(dq + 3) * 100 + jl] = kv.w;
        float* vp = Vs + jl * 68 + dq;
        vp[0] = vv.x; vp[1] = vv.y; vp[2] = vv.z; vp[3] = vv.w;
    }
    __syncthreads();

#pragma unroll 1
    for (int qq = 0; qq < 8; qq++) {
        const int il = w * 8 + qq;
        const int i = q0 + il;
        const int jj0 = lane;            // 0..31
        const int jj1 = 32 + lane;       // valid lanes 0,1
        bool v0, v1;
        if (dir == 0) {
            v0 = (i - 33 + jj0 >= 0);
            v1 = (lane < 2) && (i - 33 + jj1 >= 0);
        } else {
            v0 = (i + jj0 < SEQ);
            v1 = (lane < 2) && (i + jj1 < SEQ);
        }
        const int jl0 = il + jj0;
        const int jl1 = min(il + jj1, 96);
        float s0 = 0.f, s1 = 0.f;
        const float* qr = qs + il * 68;
#pragma unroll 8
        for (int d = 0; d < 64; d++) {
            const float qd = qr[d];
            s0 += qd * Ks[d * 100 + jl0];
            s1 += qd * Ks[d * 100 + jl1];
        }
        s0 = v0 ? (s0 * 0.125f + sbias[jj0]) : -1e30f;
        s1 = v1 ? (s1 * 0.125f + sbias[min(jj1, 33)]) : -1e30f;
        float m = fmaxf(s0, s1);
#pragma unroll
        for (int o = 16; o > 0; o >>= 1) m = fmaxf(m, __shfl_xor_sync(0xffffffffu, m, o));
        const float e0 = __expf(s0 - m), e1 = __expf(s1 - m);
        float den = e0 + e1;
#pragma unroll
        for (int o = 16; o > 0; o >>= 1) den += __shfl_xor_sync(0xffffffffu, den, o);

        // V accumulation: p(jj) broadcast from lane registers (no smem, no syncwarp)
        float o0 = 0.f, o1 = 0.f;
#pragma unroll 4
        for (int jj = 0; jj < 32; jj++) {
            const float p = __shfl_sync(0xffffffffu, e0, jj);
            const float2 vv = *(const float2*)&Vs[(il + jj) * 68 + 2 * lane];
            o0 += p * vv.x;
            o1 += p * vv.y;
        }
#pragma unroll
        for (int jj = 32; jj < WIN; jj++) {
            const float p = __shfl_sync(0xffffffffu, e1, jj - 32);
            const float2 vv = *(const float2*)&Vs[(il + jj) * 68 + 2 * lane];
            o0 += p * vv.x;
            o1 += p * vv.y;
        }
        const float inv = 1.f / den;
        const size_t oi = (size_t)dir * TOK * HID + (size_t)(b * SEQ + i) * HID + h * DK + 2 * lane;
        *(uint32_t*)&g_attn_h[oi] = pack_h2(o0 * inv, o1 * inv);
    }
}

// ---------------- init: fp16 activation (both dirs) ----------------
__global__ void init_state(const float* __restrict__ in)
{
    const size_t idx = (size_t)blockIdx.x * blockDim.x + threadIdx.x;
    const float4 v = *(const float4*)(in + idx * 4);
    const uint2 p = make_uint2(pack_h2(v.x, v.y), pack_h2(v.z, v.w));
    *(uint2*)&g_act_h[idx * 4] = p;
    *(uint2*)&g_act_h[(size_t)TOK * HID + idx * 4] = p;
}

// ---------------- launch ----------------
extern "C" void kernel_launch(void* const* d_in, const int* in_sizes, int n_in,
                              void* d_out, int out_size)
{
    const float* inputs = (const float*)d_in[0];
    const float* qkv_w  = (const float*)d_in[2];
    const float* qkv_b  = (const float*)d_in[3];
    const float* rel    = (const float*)d_in[4];
    const float* hw_w   = (const float*)d_in[5];
    const float* hw_b   = (const float*)d_in[6];
    float* out = (float*)d_out;

    float *qkvp, *yv, *st;
    __half *ah, *ath, *yh, *y2h, *wq, *wh;
    cudaGetSymbolAddress((void**)&qkvp, g_qkv);
    cudaGetSymbolAddress((void**)&yv,   g_y);
    cudaGetSymbolAddress((void**)&st,   g_st);
    cudaGetSymbolAddress((void**)&ah,   g_act_h);
    cudaGetSymbolAddress((void**)&ath,  g_attn_h);
    cudaGetSymbolAddress((void**)&yh,   g_yh);
    cudaGetSymbolAddress((void**)&y2h,  g_y2h);
    cudaGetSymbolAddress((void**)&wq,   g_wqkv);
    cudaGetSymbolAddress((void**)&wh,   g_whw);

    cudaFuncSetAttribute(gemm_fused, cudaFuncAttributeMaxDynamicSharedMemorySize, GSMEM);
    cudaFuncSetAttribute(attn_v4, cudaFuncAttributeMaxDynamicSharedMemorySize, ATT_SMEM);

    conv_all<<<8192, 256>>>(qkv_w, hw_w, wq, wh);
    init_state<<<2048, 256>>>(inputs);

    for (int l = 0; l < 2; l++) {
        const size_t QL = (size_t)l * 2 * 4 * HID * HID;
        const size_t HL = (size_t)l * 2 * 2 * 2 * HID * HID;
        const float* qb = qkv_b + (size_t)l * 2 * 4 * HID;
        const float* hb = hw_b + (size_t)l * 2 * 2 * 2 * HID;

        // QKV: 768 tiles (mode 0)
        gemm_fused<<<NCTA, 256, GSMEM>>>(
            ah, wq + QL, qb, qkvp, nullptr,
            nullptr, nullptr, nullptr,
            3 * HID, (size_t)4 * HID * HID, (size_t)4 * HID, (size_t)TOK * 3 * HID, 0, 0, 768);

        attn_v4<<<dim3(SEQ / 64, BATCH * NHEAD, 2), 256, ATT_SMEM>>>(
            rel + (size_t)l * 2 * NHEAD * WIN);

        // out projection: 256 tiles (mode 1)
        gemm_fused<<<NCTA, 256, GSMEM>>>(
            ath, wq + QL + (size_t)3 * HID * HID,
            qb + 3 * HID, yv, yh, nullptr, nullptr, nullptr,
            HID, (size_t)4 * HID * HID, (size_t)4 * HID, (size_t)TOK * HID, 1, 0, 256);

        // highway 1: 512 tiles (mode 2)
        gemm_fused<<<NCTA, 256, GSMEM>>>(
            yh, wh + HL, hb, nullptr, y2h,
            yv, nullptr, nullptr,
            2 * HID, (size_t)2 * 2 * HID * HID, (size_t)2 * 2 * HID, 0, 2, 0, 512);

        // highway 2: residual + state + concat + next-layer act (mode 3)
        gemm_fused<<<NCTA, 256, GSMEM>>>(
            y2h, wh + HL + (size_t)2 * HID * HID,
            hb + 2 * HID, nullptr, ah,
            yv, st, out + (size_t)l * TOK * 2 * HID,
            2 * HID, (size_t)2 * 2 * HID * HID, (size_t)2 * 2 * HID, 0, 3, l > 0 ? 1 : 0, 512);
    }
}

// round 11
// speedup vs baseline: 1.3737x; 1.0476x over previous
#include <cuda_runtime.h>
#include <cuda_fp16.h>
#include <cstdint>
#include <cstddef>

#define NHEAD 8
#define HID 512
#define DK 64
#define SEQ 1024
#define BATCH 4
#define TOK 4096
#define WIN 34
#define KDIM 512

#define BK 64
#define OFF_B 16384
#define STAGE_B 32768                  // A | B
#define GSMEM (3 * STAGE_B)            // 98304, 3-stage pipeline
#define NCTA 296

// ---------------- scratch ----------------
__device__ float g_st  [2ull * TOK * HID];
__device__ float g_qkv [2ull * TOK * 3 * HID];
__device__ float g_y   [2ull * TOK * HID];
__device__ __half g_act_h [2ull * TOK * HID];
__device__ __half g_attn_h[2ull * TOK * HID];
__device__ __half g_yh    [2ull * TOK * HID];
__device__ __half g_y2h   [2ull * TOK * HID];
__device__ __half g_wqkv  [4194304];
__device__ __half g_whw   [4194304];

// ---------------- helpers ----------------
__device__ __forceinline__ uint32_t s2u(const void* p) {
    uint32_t a;
    asm("{ .reg .u64 t; cvta.to.shared.u64 t, %1; cvt.u32.u64 %0, t; }" : "=r"(a) : "l"(p));
    return a;
}
__device__ __forceinline__ void cpasync16(uint32_t dst, const void* src) {
    asm volatile("cp.async.cg.shared.global [%0], [%1], 16;" :: "r"(dst), "l"(src));
}
__device__ __forceinline__ void ldmx4(uint32_t* d, uint32_t a) {
    asm volatile("ldmatrix.sync.aligned.m8n8.x4.shared.b16 {%0,%1,%2,%3}, [%4];"
        : "=r"(d[0]), "=r"(d[1]), "=r"(d[2]), "=r"(d[3]) : "r"(a));
}
__device__ __forceinline__ void mma16816(float* c, const uint32_t* a, const uint32_t* b) {
    asm volatile("mma.sync.aligned.m16n8k16.row.col.f32.f16.f16.f32 "
        "{%0,%1,%2,%3}, {%4,%5,%6,%7}, {%8,%9}, {%0,%1,%2,%3};"
        : "+f"(c[0]), "+f"(c[1]), "+f"(c[2]), "+f"(c[3])
        : "r"(a[0]), "r"(a[1]), "r"(a[2]), "r"(a[3]), "r"(b[0]), "r"(b[1]));
}
__device__ __forceinline__ uint32_t pack_h2(float x, float y) {
    __half2 t = __floats2half2_rn(x, y);
    return *(uint32_t*)&t;
}

// ---------------- prep (merged): weight conversion + activation init ----------
// grid 10240: [0,4096) qkv weights, [4096,8192) highway weights, [8192,10240) init
__global__ void prep_all(const float* __restrict__ qkvw, const float* __restrict__ hww,
                         const float* __restrict__ in,
                         __half* __restrict__ dq, __half* __restrict__ dh)
{
    const size_t bi = blockIdx.x;
    if (bi < 4096) {
        const size_t i = bi * blockDim.x + threadIdx.x;
        float4 v = ((const float4*)qkvw)[i];
        *(uint2*)(dq + 4 * i) = make_uint2(pack_h2(v.x, v.y), pack_h2(v.z, v.w));
    } else if (bi < 8192) {
        const size_t idx = (bi - 4096) * blockDim.x + threadIdx.x;
        const size_t m   = idx >> 17;
        const size_t rem = idx & 131071;
        const int    r   = (int)(rem >> 7);
        const size_t c4  = rem & 127;
        const int dr = (r < 512) ? (2 * r) : (2 * (r - 512) + 1);
        float4 v = ((const float4*)hww)[idx];
        const size_t d = (m << 17) + (size_t)dr * 128 + c4;
        *(uint2*)(dh + 4 * d) = make_uint2(pack_h2(v.x, v.y), pack_h2(v.z, v.w));
    } else {
        const size_t idx = (bi - 8192) * blockDim.x + threadIdx.x;
        const float4 v = *(const float4*)(in + idx * 4);
        const uint2 p = make_uint2(pack_h2(v.x, v.y), pack_h2(v.z, v.w));
        *(uint2*)&g_act_h[idx * 4] = p;
        *(uint2*)&g_act_h[(size_t)TOK * HID + idx * 4] = p;
    }
}

// ---------------- persistent fused HMMA GEMM (R8/R10 config, unchanged) -----
__global__ __launch_bounds__(256, 2)
void gemm_fused(const __half* __restrict__ A, const __half* __restrict__ B,
                const float* __restrict__ bias, float* __restrict__ C,
                __half* __restrict__ Sh,
                float* __restrict__ Yv, float* __restrict__ St, float* __restrict__ Out,
                int N, size_t sB, size_t sbias, size_t sC, int mode, int add_res,
                int ntiles)
{
    extern __shared__ char smem[];
    const uint32_t sbase = s2u(smem);
    const int tid = threadIdx.x, lane = tid & 31, wid = tid >> 5;
    const int wm = wid & 1, wn = wid >> 1;

    const int bx = (int)blockIdx.x;
    const int nt = (bx < ntiles) ? ((ntiles - 1 - bx) / (int)gridDim.x + 1) : 0;
    if (nt == 0) return;
    const int total = nt * 8;

    const int r  = tid >> 1;
    const int c0 = (tid & 1) * 4;
    const uint32_t r7 = (uint32_t)(r & 7);
    uint32_t swz[4];
#pragma unroll
    for (int u = 0; u < 4; u++)
        swz[u] = (uint32_t)r * 128 + ((((uint32_t)(c0 + u)) ^ r7) << 4);

    const int m8 = lane >> 3, l7 = lane & 7;
    const uint32_t a_row = (uint32_t)(wm * 64 + (m8 & 1) * 8 + l7) * 128;
    const uint32_t b_row = (uint32_t)(wn * 32 + (m8 >> 1) * 8 + l7) * 128;
    uint32_t acol[4], bcol[4];
#pragma unroll
    for (int kk = 0; kk < 4; kk++) {
        acol[kk] = ((uint32_t)(kk * 2 + (m8 >> 1)) ^ (uint32_t)l7) << 4;
        bcol[kk] = ((uint32_t)(kk * 2 + (m8 & 1)) ^ (uint32_t)l7) << 4;
    }

    float acc[4][4][4];
#pragma unroll
    for (int i = 0; i < 4; i++)
#pragma unroll
        for (int j = 0; j < 4; j++)
#pragma unroll
            for (int k = 0; k < 4; k++) acc[i][j][k] = 0.f;

#define LOAD_G(g) do {                                                             \
        const int _t = bx + ((g) >> 3) * (int)gridDim.x;                           \
        const int _dir = _t & 1, _u = _t >> 1;                                     \
        const int _bm = (_u & 31) * 128, _bn = (_u >> 5) * 128;                    \
        const int _ke = ((g) & 7) * BK + c0 * 8;                                   \
        const __half* _Ap = A + (size_t)_dir * (TOK * KDIM)                        \
                              + (size_t)(_bm + r) * KDIM + _ke;                    \
        const __half* _Bp = B + (size_t)_dir * sB + (size_t)(_bn + r) * KDIM + _ke;\
        const uint32_t _sb = sbase + (uint32_t)((g) % 3) * STAGE_B;                \
        cpasync16(_sb + swz[0],         _Ap);                                      \
        cpasync16(_sb + swz[1],         _Ap + 8);                                  \
        cpasync16(_sb + swz[2],         _Ap + 16);                                 \
        cpasync16(_sb + swz[3],         _Ap + 24);                                 \
        cpasync16(_sb + OFF_B + swz[0], _Bp);                                      \
        cpasync16(_sb + OFF_B + swz[1], _Bp + 8);                                  \
        cpasync16(_sb + OFF_B + swz[2], _Bp + 16);                                 \
        cpasync16(_sb + OFF_B + swz[3], _Bp + 24);                                 \
        asm volatile("cp.async.commit_group;" ::: "memory");                       \
    } while (0)

    LOAD_G(0);
    LOAD_G(1);

    const int gr = lane >> 2, gc = (lane & 3) * 2;

#pragma unroll 1
    for (int g = 0; g < total; g++) {
        if (g < total - 1) asm volatile("cp.async.wait_group 1;" ::: "memory");
        else               asm volatile("cp.async.wait_group 0;" ::: "memory");
        __syncthreads();
        if (g + 2 < total) LOAD_G(g + 2);

        const uint32_t sb = sbase + (uint32_t)(g % 3) * STAGE_B;
#pragma unroll
        for (int kk = 0; kk < 4; kk++) {
            uint32_t a[4][4], b[2][4];
#pragma unroll
            for (int nj = 0; nj < 2; nj++)
                ldmx4(b[nj], sb + OFF_B + b_row + nj * 2048 + bcol[kk]);
#pragma unroll
            for (int mi = 0; mi < 4; mi++)
                ldmx4(a[mi], sb + a_row + mi * 2048 + acol[kk]);
#pragma unroll
            for (int mi = 0; mi < 4; mi++)
#pragma unroll
                for (int ni = 0; ni < 4; ni++)
                    mma16816(acc[mi][ni], a[mi], &b[ni >> 1][(ni & 1) * 2]);
        }

        if ((g & 7) == 7) {
            const int t = bx + (g >> 3) * (int)gridDim.x;
            const int dir = t & 1, u = t >> 1;
            const int bm = (u & 31) * 128, bn = (u >> 5) * 128;
            const float* bs = bias + (size_t)dir * sbias;

            if (mode <= 1) {
                float* Cp = C + (size_t)dir * sC;
                __half* SH = Sh ? (Sh + (size_t)dir * sC) : nullptr;
#pragma unroll
                for (int mi = 0; mi < 4; mi++) {
#pragma unroll
                    for (int ni = 0; ni < 4; ni++) {
                        const int row0 = bm + wm * 64 + mi * 16 + gr;
                        const int col  = bn + wn * 32 + ni * 8 + gc;
                        const float b0 = bs[col], b1 = bs[col + 1];
                        const float v00 = acc[mi][ni][0] + b0, v01 = acc[mi][ni][1] + b1;
                        const float v10 = acc[mi][ni][2] + b0, v11 = acc[mi][ni][3] + b1;
                        *(float2*)&Cp[(size_t)row0 * N + col]       = make_float2(v00, v01);
                        *(float2*)&Cp[(size_t)(row0 + 8) * N + col] = make_float2(v10, v11);
                        if (mode == 1) {
                            *(uint32_t*)&SH[(size_t)row0 * N + col]       = pack_h2(v00, v01);
                            *(uint32_t*)&SH[(size_t)(row0 + 8) * N + col] = pack_h2(v10, v11);
                        }
                    }
                }
            } else {
                float* Y = Yv + (size_t)dir * TOK * HID;
                float* S = St ? (St + (size_t)dir * TOK * HID) : nullptr;
                __half* SH = Sh + (size_t)dir * TOK * HID;
#pragma unroll
                for (int mi = 0; mi < 4; mi++) {
#pragma unroll
                    for (int ni = 0; ni < 4; ni++) {
                        const int row0 = bm + wm * 64 + mi * 16 + gr;
                        const int col  = bn + wn * 32 + ni * 8 + gc;
                        const int j    = col >> 1;
                        const float bnl = bs[j], bgt = bs[j + HID];
#pragma unroll
                        for (int rr = 0; rr < 2; rr++) {
                            const int row = row0 + rr * 8;
                            const float n = acc[mi][ni][rr * 2]     + bnl;
                            const float gg = acc[mi][ni][rr * 2 + 1] + bgt;
                            const size_t o = (size_t)row * HID + j;
                            const float yo = Y[o];
                            const float s = 1.f / (1.f + __expf(-gg));
                            float v = s * yo + (1.f - s) * fmaxf(n, 0.f);
                            if (mode == 2) {
                                Y[o] = v;
                            } else {
                                if (add_res) v += S[o];
                                S[o] = v;
                                Out[(size_t)row * (2 * HID) + (size_t)dir * HID + j] = v;
                            }
                            SH[o] = __float2half(v);
                        }
                    }
                }
            }
#pragma unroll
            for (int i = 0; i < 4; i++)
#pragma unroll
                for (int j = 0; j < 4; j++)
#pragma unroll
                    for (int k = 0; k < 4; k++) acc[i][j][k] = 0.f;
        }
    }
#undef LOAD_G
}

// ---------------- banded local attention v5 ---------------------------------
// Removes the wasteful per-query s1 dot: one combined extras pass computes all
// 16 extra scores (8 queries x jj=32,33) per warp; phase B fetches them by shfl.
// q broadcasts vectorized to float4. All math fp32, identical to v4 results.
#define ATT_SMEM (17384 * 4)
__global__ void attn_v5(const float* __restrict__ rel_l)
{
    extern __shared__ float sm[];
    float* Ks = sm;               // [64][100] transposed K: d-major
    float* Vs = sm + 6400;        // [97][68]
    float* qs = sm + 12996;       // [64][68]
    float* sbias = sm + 17348;    // [34]

    const int dir = blockIdx.z;
    const int bh = blockIdx.y;
    const int b = bh >> 3, h = bh & 7;
    const int q0 = blockIdx.x * 64;
    const int tid = threadIdx.x, w = tid >> 5, lane = tid & 31;
    const int W0 = (dir == 0) ? (q0 - 33) : q0;

    const float* base = g_qkv + (size_t)dir * TOK * (3 * HID)
                              + (size_t)(b * SEQ) * (3 * HID) + h * DK;

    if (tid < WIN)
        sbias[tid] = rel_l[((size_t)dir * NHEAD + h) * WIN + tid];

    // load q tile
    for (int idx = tid; idx < 64 * 16; idx += 256) {
        const int row = idx >> 4, dq = (idx & 15) * 4;
        const float4 v = *(const float4*)(base + (size_t)(q0 + row) * 1536 + dq);
        float* qp = qs + row * 68 + dq;
        qp[0] = v.x; qp[1] = v.y; qp[2] = v.z; qp[3] = v.w;
    }
    // load K (transposed) and V window
    for (int idx = tid; idx < 97 * 16; idx += 256) {
        const int jl = idx >> 4, dq = (idx & 15) * 4;
        const int j = W0 + jl;
        float4 kv = make_float4(0.f, 0.f, 0.f, 0.f);
        float4 vv = make_float4(0.f, 0.f, 0.f, 0.f);
        if (j >= 0 && j < SEQ) {
            kv = *(const float4*)(base + HID + (size_t)j * 1536 + dq);
            vv = *(const float4*)(base + 2 * HID + (size_t)j * 1536 + dq);
        }
        Ks[(dq + 0) * 100 + jl] = kv.x;
        Ks[(dq + 1) * 100 + jl] = kv.y;
        Ks[(dq + 2) * 100 + jl] = kv.z;
        Ks[(dq + 3) * 100 + jl] = kv.w;
        float* vp = Vs + jl * 68 + dq;
        vp[0] = vv.x; vp[1] = vv.y; vp[2] = vv.z; vp[3] = vv.w;
    }
    __syncthreads();

    // ---- extras pass: lane el<16 -> (query qqe = el>>1, jj = 32+(el&1)) ----
    float sx;
    {
        const int el = lane & 15;
        const int qqe = el >> 1;
        const int jje = 32 + (el & 1);
        const int ile = w * 8 + qqe;
        const int ie = q0 + ile;
        const bool ve = (dir == 0) ? (ie - 33 + jje >= 0) : (ie + jje < SEQ);
        const int jle = ile + jje;           // <= 96
        const float* qe = qs + ile * 68;
        float s = 0.f;
#pragma unroll 8
        for (int d = 0; d < 64; d++)
            s += qe[d] * Ks[d * 100 + jle];
        sx = ve ? (s * 0.125f + sbias[jje]) : -1e30f;
    }

#pragma unroll 1
    for (int qq = 0; qq < 8; qq++) {
        const int il = w * 8 + qq;
        const int i = q0 + il;
        const int jj0 = lane;                // 0..31
        const bool v0 = (dir == 0) ? (i - 33 + jj0 >= 0) : (i + jj0 < SEQ);
        const int jl0 = il + jj0;            // <= 94
        float s0 = 0.f;
        const float* qr = qs + il * 68;
#pragma unroll 4
        for (int d4 = 0; d4 < 64; d4 += 4) {
            const float4 qv = *(const float4*)(qr + d4);
            s0 += qv.x * Ks[(d4 + 0) * 100 + jl0];
            s0 += qv.y * Ks[(d4 + 1) * 100 + jl0];
            s0 += qv.z * Ks[(d4 + 2) * 100 + jl0];
            s0 += qv.w * Ks[(d4 + 3) * 100 + jl0];
        }
        s0 = v0 ? (s0 * 0.125f + sbias[jj0]) : -1e30f;

        const float se0 = __shfl_sync(0xffffffffu, sx, 2 * qq);
        const float se1 = __shfl_sync(0xffffffffu, sx, 2 * qq + 1);

        float m = fmaxf(s0, fmaxf(se0, se1));
#pragma unroll
        for (int o = 16; o > 0; o >>= 1) m = fmaxf(m, __shfl_xor_sync(0xffffffffu, m, o));
        const float e0 = __expf(s0 - m);
        const float ee0 = __expf(se0 - m);
        const float ee1 = __expf(se1 - m);
        float den = e0;
#pragma unroll
        for (int o = 16; o > 0; o >>= 1) den += __shfl_xor_sync(0xffffffffu, den, o);
        den += ee0 + ee1;

        // V accumulation: p(jj) broadcast via shfl; extras applied directly
        float o0 = 0.f, o1 = 0.f;
#pragma unroll 4
        for (int jj = 0; jj < 32; jj++) {
            const float p = __shfl_sync(0xffffffffu, e0, jj);
            const float2 vv = *(const float2*)&Vs[(il + jj) * 68 + 2 * lane];
            o0 += p * vv.x;
            o1 += p * vv.y;
        }
        {
            const float2 v32 = *(const float2*)&Vs[(il + 32) * 68 + 2 * lane];
            const float2 v33 = *(const float2*)&Vs[(il + 33) * 68 + 2 * lane];
            o0 += ee0 * v32.x + ee1 * v33.x;
            o1 += ee0 * v32.y + ee1 * v33.y;
        }
        const float inv = 1.f / den;
        const size_t oi = (size_t)dir * TOK * HID + (size_t)(b * SEQ + i) * HID + h * DK + 2 * lane;
        *(uint32_t*)&g_attn_h[oi] = pack_h2(o0 * inv, o1 * inv);
    }
}

// ---------------- launch ----------------
extern "C" void kernel_launch(void* const* d_in, const int* in_sizes, int n_in,
                              void* d_out, int out_size)
{
    const float* inputs = (const float*)d_in[0];
    const float* qkv_w  = (const float*)d_in[2];
    const float* qkv_b  = (const float*)d_in[3];
    const float* rel    = (const float*)d_in[4];
    const float* hw_w   = (const float*)d_in[5];
    const float* hw_b   = (const float*)d_in[6];
    float* out = (float*)d_out;

    float *qkvp, *yv, *st;
    __half *ah, *ath, *yh, *y2h, *wq, *wh;
    cudaGetSymbolAddress((void**)&qkvp, g_qkv);
    cudaGetSymbolAddress((void**)&yv,   g_y);
    cudaGetSymbolAddress((void**)&st,   g_st);
    cudaGetSymbolAddress((void**)&ah,   g_act_h);
    cudaGetSymbolAddress((void**)&ath,  g_attn_h);
    cudaGetSymbolAddress((void**)&yh,   g_yh);
    cudaGetSymbolAddress((void**)&y2h,  g_y2h);
    cudaGetSymbolAddress((void**)&wq,   g_wqkv);
    cudaGetSymbolAddress((void**)&wh,   g_whw);

    cudaFuncSetAttribute(gemm_fused, cudaFuncAttributeMaxDynamicSharedMemorySize, GSMEM);
    cudaFuncSetAttribute(attn_v5, cudaFuncAttributeMaxDynamicSharedMemorySize, ATT_SMEM);

    prep_all<<<10240, 256>>>(qkv_w, hw_w, inputs, wq, wh);

    for (int l = 0; l < 2; l++) {
        const size_t QL = (size_t)l * 2 * 4 * HID * HID;
        const size_t HL = (size_t)l * 2 * 2 * 2 * HID * HID;
        const float* qb = qkv_b + (size_t)l * 2 * 4 * HID;
        const float* hb = hw_b + (size_t)l * 2 * 2 * 2 * HID;

        // QKV: 768 tiles (mode 0)
        gemm_fused<<<NCTA, 256, GSMEM>>>(
            ah, wq + QL, qb, qkvp, nullptr,
            nullptr, nullptr, nullptr,
            3 * HID, (size_t)4 * HID * HID, (size_t)4 * HID, (size_t)TOK * 3 * HID, 0, 0, 768);

        attn_v5<<<dim3(SEQ / 64, BATCH * NHEAD, 2), 256, ATT_SMEM>>>(
            rel + (size_t)l * 2 * NHEAD * WIN);

        // out projection: 256 tiles (mode 1)
        gemm_fused<<<NCTA, 256, GSMEM>>>(
            ath, wq + QL + (size_t)3 * HID * HID,
            qb + 3 * HID, yv, yh, nullptr, nullptr, nullptr,
            HID, (size_t)4 * HID * HID, (size_t)4 * HID, (size_t)TOK * HID, 1, 0, 256);

        // highway 1: 512 tiles (mode 2)
        gemm_fused<<<NCTA, 256, GSMEM>>>(
            yh, wh + HL, hb, nullptr, y2h,
            yv, nullptr, nullptr,
            2 * HID, (size_t)2 * 2 * HID * HID, (size_t)2 * 2 * HID, 0, 2, 0, 512);

        // highway 2: residual + state + concat + next-layer act (mode 3)
        gemm_fused<<<NCTA, 256, GSMEM>>>(
            y2h, wh + HL + (size_t)2 * HID * HID,
            hb + 2 * HID, nullptr, ah,
            yv, st, out + (size_t)l * TOK * 2 * HID,
            2 * HID, (size_t)2 * 2 * HID * HID, (size_t)2 * 2 * HID, 0, 3, l > 0 ? 1 : 0, 512);
    }
}